// round 3
// baseline (speedup 1.0000x reference)
#include <cuda_runtime.h>
#include <math.h>

typedef unsigned long long u64;

// ---------------- capacities (P*M = P*N = 32768 here; generous headroom) ----
#define CAP 65536
#define QCH 2048   // queries per work item (256 thr * 8 qpt = 4 packed u64/thread)
#define TSL 256    // targets per work item (shared tile = 8KB)
#define NBLK 296   // persistent grid (2 CTAs/SM on 148 SMs)
#define NRED 128   // reduce blocks

__device__ float    g_tf[8 * 16];
__device__ float    g_cadT[CAP * 8];   // transformed cad, target fmt [x,x,y,y,z,z,h,h], h=|v|^2/2
__device__ float    g_camT[CAP * 8];   // cam, target fmt
__device__ float4   g_cadQ[CAP];       // transformed cad, query fmt (x,y,z,|v|^2)
__device__ float4   g_camQ[CAP];
__device__ unsigned g_minbuf[2 * CAP]; // per-(dir,p,query) min d2 as uint bits
__device__ float    g_partial[NRED];
__device__ unsigned g_ticket;

// ---------------- f32x2 helpers ---------------------------------------------
__device__ __forceinline__ u64 pack2(float lo, float hi) {
    u64 r; asm("mov.b64 %0, {%1, %2};" : "=l"(r) : "f"(lo), "f"(hi)); return r;
}
__device__ __forceinline__ void unpack2(u64 v, float& lo, float& hi) {
    asm("mov.b64 {%0, %1}, %2;" : "=f"(lo), "=f"(hi) : "l"(v));
}
__device__ __forceinline__ u64 fma2(u64 a, u64 b, u64 c) {
    u64 d; asm("fma.rn.f32x2 %0, %1, %2, %3;" : "=l"(d) : "l"(a), "l"(b), "l"(c)); return d;
}

// ---------------- kernel 1: quat -> transforms ------------------------------
__global__ void k_tf(const float* __restrict__ quat, const float* __restrict__ tra,
                     float* __restrict__ out, int P, int write_out) {
    int p = threadIdx.x;
    if (p >= P) return;
    float a = quat[4 * p + 0], b = quat[4 * p + 1], c = quat[4 * p + 2], d = quat[4 * p + 3];
    float inv = rsqrtf(a * a + b * b + c * c + d * d);
    a *= inv; b *= inv; c *= inv; d *= inv;
    float tf[16];
    tf[0]  = 1.f - 2.f * (c * c + d * d);
    tf[1]  = 2.f * (b * c - a * d);
    tf[2]  = 2.f * (a * c + b * d);
    tf[3]  = tra[3 * p + 0];
    tf[4]  = 2.f * (b * c + a * d);
    tf[5]  = 1.f - 2.f * (b * b + d * d);
    tf[6]  = 2.f * (c * d - a * b);
    tf[7]  = tra[3 * p + 1];
    tf[8]  = 2.f * (b * d - a * c);
    tf[9]  = 2.f * (a * b + c * d);
    tf[10] = 1.f - 2.f * (b * b + c * c);
    tf[11] = tra[3 * p + 2];
    tf[12] = 0.f; tf[13] = 0.f; tf[14] = 0.f; tf[15] = 1.f;
#pragma unroll
    for (int i = 0; i < 16; i++) {
        g_tf[p * 16 + i] = tf[i];
        if (write_out) out[1 + p * 16 + i] = tf[i];
    }
}

// ---------------- kernel 2: prepare point buffers + init minbuf -------------
__global__ void k_prep(const float* __restrict__ cad, const float* __restrict__ cam,
                       int P, int M, int N, int total) {
    int idx = blockIdx.x * blockDim.x + threadIdx.x;
    if (idx >= total) return;
    g_minbuf[idx] = 0x7f800000u;  // +inf

    float vx, vy, vz;
    if (idx < P * M) {
        int p = idx / M;
        const float* pt = cad + (size_t)idx * 3;
        const float* tf = g_tf + p * 16;
        float x = pt[0], y = pt[1], z = pt[2];
        vx = tf[0] * x + tf[1] * y + tf[2]  * z + tf[3];
        vy = tf[4] * x + tf[5] * y + tf[6]  * z + tf[7];
        vz = tf[8] * x + tf[9] * y + tf[10] * z + tf[11];
        float n2 = vx * vx + vy * vy + vz * vz;
        float* T = g_cadT + (size_t)idx * 8;
        T[0] = vx; T[1] = vx; T[2] = vy; T[3] = vy;
        T[4] = vz; T[5] = vz; T[6] = 0.5f * n2; T[7] = 0.5f * n2;
        g_cadQ[idx] = make_float4(vx, vy, vz, n2);
    } else {
        int j = idx - P * M;
        const float* pt = cam + (size_t)j * 3;
        vx = pt[0]; vy = pt[1]; vz = pt[2];
        float n2 = vx * vx + vy * vy + vz * vz;
        float* T = g_camT + (size_t)j * 8;
        T[0] = vx; T[1] = vx; T[2] = vy; T[3] = vy;
        T[4] = vz; T[5] = vz; T[6] = 0.5f * n2; T[7] = 0.5f * n2;
        g_camQ[j] = make_float4(vx, vy, vz, n2);
    }
}

// ---------------- kernel 2.5: reset ticket (also aligns ncu capture) --------
__global__ void k_tick() {
    if (threadIdx.x == 0) g_ticket = 0u;
}

// ---------------- kernel 3: chamfer (hot; persistent + work stealing) -------
__global__ void __launch_bounds__(256, 2) k_chamfer(int P, int M, int N,
                                                    int qcA, int tsA, int qcB, int tsB) {
    __shared__ __align__(16) float tile[TSL * 8];
    __shared__ int s_item;

    const int tid = threadIdx.x;
    const float INF = __int_as_float(0x7f800000);
    const int itemsA = P * qcA * tsA;
    const int itemsB = P * qcB * tsB;
    const int totalItems = itemsA + itemsB;

    for (;;) {
        __syncthreads();            // prev iter fully done with tile & s_item
        if (tid == 0) s_item = (int)atomicAdd(&g_ticket, 1u);
        __syncthreads();
        int item = s_item;
        if (item >= totalItems) break;

        int p, qc, sl, nq, nt, minoff;
        const float4* Q;
        const float*  T;
        if (item < itemsA) {
            p = item / (qcA * tsA); int r = item % (qcA * tsA); qc = r / tsA; sl = r % tsA;
            nq = M; nt = N;
            Q = g_cadQ + (size_t)p * M;
            T = g_camT + (size_t)p * N * 8;
            minoff = p * M;
        } else {
            int b1 = item - itemsA;
            p = b1 / (qcB * tsB); int r = b1 % (qcB * tsB); qc = r / tsB; sl = r % tsB;
            nq = N; nt = M;
            Q = g_camQ + (size_t)p * N;
            T = g_cadT + (size_t)p * M * 8;
            minoff = P * M + p * N;
        }

        // ---- load this thread's 8 query points (4 packed pairs) ----
        u64 qnx[4], qny[4], qnz[4];
        float mn0[4], mn1[4], x2a[4], x2b[4];
#pragma unroll
        for (int k = 0; k < 4; k++) {
            int i0 = qc * QCH + (2 * k) * 256 + tid;
            int i1 = i0 + 256;
            float4 A = (i0 < nq) ? Q[i0] : make_float4(0.f, 0.f, 0.f, INF);
            float4 B = (i1 < nq) ? Q[i1] : make_float4(0.f, 0.f, 0.f, INF);
            qnx[k] = pack2(-A.x, -B.x);
            qny[k] = pack2(-A.y, -B.y);
            qnz[k] = pack2(-A.z, -B.z);
            x2a[k] = A.w; x2b[k] = B.w;
            mn0[k] = INF; mn1[k] = INF;
        }

        // ---- cooperative tile load (coalesced float4s) ----
        int tb = sl * TSL;
        int cnt = min(TSL, nt - tb);
        {
            const float4* src = (const float4*)(T + (size_t)tb * 8);
            float4* dst = (float4*)tile;
            for (int v = tid; v < cnt * 2; v += 256) dst[v] = src[v];
        }
        __syncthreads();

        // ---- main loop: 2 targets x 8 queries per iteration ----
        int j = 0;
        for (; j + 2 <= cnt; j += 2) {
            ulonglong2 a0 = *(const ulonglong2*)(tile + j * 8);          // t0 {xx,yy}
            ulonglong2 a1 = *(const ulonglong2*)(tile + j * 8 + 4);      // t0 {zz,hh}
            ulonglong2 b0 = *(const ulonglong2*)(tile + j * 8 + 8);      // t1 {xx,yy}
            ulonglong2 b1 = *(const ulonglong2*)(tile + j * 8 + 12);     // t1 {zz,hh}
#pragma unroll
            for (int k = 0; k < 4; k++) {
                u64 gA = fma2(qnx[k], a0.x, a1.y);
                u64 gB = fma2(qnx[k], b0.x, b1.y);
                gA = fma2(qny[k], a0.y, gA);
                gB = fma2(qny[k], b0.y, gB);
                gA = fma2(qnz[k], a1.x, gA);
                gB = fma2(qnz[k], b1.x, gB);
                float a_lo, a_hi, b_lo, b_hi;
                unpack2(gA, a_lo, a_hi);
                unpack2(gB, b_lo, b_hi);
                mn0[k] = fminf(mn0[k], fminf(a_lo, b_lo));
                mn1[k] = fminf(mn1[k], fminf(a_hi, b_hi));
            }
        }
        for (; j < cnt; j++) {
            ulonglong2 a0 = *(const ulonglong2*)(tile + j * 8);
            ulonglong2 a1 = *(const ulonglong2*)(tile + j * 8 + 4);
#pragma unroll
            for (int k = 0; k < 4; k++) {
                u64 gA = fma2(qnx[k], a0.x, a1.y);
                gA = fma2(qny[k], a0.y, gA);
                gA = fma2(qnz[k], a1.x, gA);
                float a_lo, a_hi;
                unpack2(gA, a_lo, a_hi);
                mn0[k] = fminf(mn0[k], a_lo);
                mn1[k] = fminf(mn1[k], a_hi);
            }
        }

        // ---- combine across slices: d2 = 2*g + |q|^2 (>=0), bitwise uint min ----
#pragma unroll
        for (int k = 0; k < 4; k++) {
            int i0 = qc * QCH + (2 * k) * 256 + tid;
            int i1 = i0 + 256;
            if (i0 < nq) {
                float d2 = fmaxf(fmaf(2.f, mn0[k], x2a[k]), 0.f);
                atomicMin(g_minbuf + minoff + i0, __float_as_uint(d2));
            }
            if (i1 < nq) {
                float d2 = fmaxf(fmaf(2.f, mn1[k], x2b[k]), 0.f);
                atomicMin(g_minbuf + minoff + i1, __float_as_uint(d2));
            }
        }
    }
}

// ---------------- kernel 4: weighted sqrt-sum partials -----------------------
__global__ void k_red(const float* __restrict__ w, int P, int M, int N) {
    __shared__ float sh[256];
    int total = P * (M + N);
    float s = 0.f;
    for (int e = blockIdx.x * 256 + threadIdx.x; e < total; e += NRED * 256) {
        int p; float invc;
        if (e < P * M) { p = e / M; invc = 1.0f / (float)M; }
        else           { p = (e - P * M) / N; invc = 1.0f / (float)N; }
        s += w[p] * invc * sqrtf(__uint_as_float(g_minbuf[e]));
    }
    sh[threadIdx.x] = s;
    __syncthreads();
    for (int o = 128; o > 0; o >>= 1) {
        if (threadIdx.x < o) sh[threadIdx.x] += sh[threadIdx.x + o];
        __syncthreads();
    }
    if (threadIdx.x == 0) g_partial[blockIdx.x] = sh[0];
}

// ---------------- kernel 5: deterministic final sum --------------------------
__global__ void k_fin(float* __restrict__ out) {
    if (threadIdx.x == 0) {
        float s = 0.f;
        for (int i = 0; i < NRED; i++) s += g_partial[i];
        out[0] = s;
    }
}

// ---------------- launcher ----------------------------------------------------
extern "C" void kernel_launch(void* const* d_in, const int* in_sizes, int n_in,
                              void* d_out, int out_size) {
    const float* cam  = (const float*)d_in[0];  // (P,N,3)
    const float* cad  = (const float*)d_in[1];  // (P,M,3)
    const float* wgt  = (const float*)d_in[2];  // (P,)
    const float* quat = (const float*)d_in[3];  // (P,4)
    const float* tra  = (const float*)d_in[4];  // (P,3,1)
    float* out = (float*)d_out;

    int P = in_sizes[2];
    int N = in_sizes[0] / (3 * P);
    int M = in_sizes[1] / (3 * P);
    int write_out = (out_size >= 1 + 16 * P) ? 1 : 0;

    k_tf<<<1, 32>>>(quat, tra, out, P, write_out);              // launch offset 0

    int total = P * (M + N);
    k_prep<<<(total + 255) / 256, 256>>>(cad, cam, P, M, N, total);  // offset 1

    k_tick<<<1, 32>>>();                                        // offset 2 (aligns ncu)

    int qcA = (M + QCH - 1) / QCH, tsA = (N + TSL - 1) / TSL;
    int qcB = (N + QCH - 1) / QCH, tsB = (M + TSL - 1) / TSL;
    k_chamfer<<<NBLK, 256>>>(P, M, N, qcA, tsA, qcB, tsB);      // offset 3 (profiled)

    k_red<<<NRED, 256>>>(wgt, P, M, N);                         // offset 4
    k_fin<<<1, 1>>>(out);                                       // offset 5
}

// round 4
// speedup vs baseline: 1.0725x; 1.0725x over previous
#include <cuda_runtime.h>
#include <math.h>

typedef unsigned long long u64;

// ---------------- capacities (P*M = P*N = 32768 here; generous headroom) ----
#define CAP 65536
#define QCH 2048   // queries per work item (256 thr * 8 qpt = 4 packed u64/thread)
#define TSL 128    // targets per work item (shared tile = 4KB)
#define NBLK 296   // persistent grid (2 CTAs/SM on 148 SMs)
#define NRED 128   // reduce blocks

__device__ float    g_tf[8 * 16];
__device__ float    g_cadT[CAP * 8];   // transformed cad, target fmt [x,x,y,y,z,z,h,h], h=|v|^2/2
__device__ float    g_camT[CAP * 8];   // cam, target fmt
__device__ float4   g_cadQ[CAP];       // transformed cad, query fmt (x,y,z,|v|^2)
__device__ float4   g_camQ[CAP];
__device__ unsigned g_minbuf[2 * CAP]; // per-(dir,p,query) min d2 as uint bits
__device__ float    g_partial[NRED];
__device__ unsigned g_ticket;

// ---------------- f32x2 helpers ---------------------------------------------
__device__ __forceinline__ u64 pack2(float lo, float hi) {
    u64 r; asm("mov.b64 %0, {%1, %2};" : "=l"(r) : "f"(lo), "f"(hi)); return r;
}
__device__ __forceinline__ void unpack2(u64 v, float& lo, float& hi) {
    asm("mov.b64 {%0, %1}, %2;" : "=f"(lo), "=f"(hi) : "l"(v));
}
__device__ __forceinline__ u64 fma2(u64 a, u64 b, u64 c) {
    u64 d; asm("fma.rn.f32x2 %0, %1, %2, %3;" : "=l"(d) : "l"(a), "l"(b), "l"(c)); return d;
}

// ---------------- kernel 1: quat -> transforms ------------------------------
__global__ void k_tf(const float* __restrict__ quat, const float* __restrict__ tra,
                     float* __restrict__ out, int P, int write_out) {
    int p = threadIdx.x;
    if (p >= P) return;
    float a = quat[4 * p + 0], b = quat[4 * p + 1], c = quat[4 * p + 2], d = quat[4 * p + 3];
    float inv = rsqrtf(a * a + b * b + c * c + d * d);
    a *= inv; b *= inv; c *= inv; d *= inv;
    float tf[16];
    tf[0]  = 1.f - 2.f * (c * c + d * d);
    tf[1]  = 2.f * (b * c - a * d);
    tf[2]  = 2.f * (a * c + b * d);
    tf[3]  = tra[3 * p + 0];
    tf[4]  = 2.f * (b * c + a * d);
    tf[5]  = 1.f - 2.f * (b * b + d * d);
    tf[6]  = 2.f * (c * d - a * b);
    tf[7]  = tra[3 * p + 1];
    tf[8]  = 2.f * (b * d - a * c);
    tf[9]  = 2.f * (a * b + c * d);
    tf[10] = 1.f - 2.f * (b * b + c * c);
    tf[11] = tra[3 * p + 2];
    tf[12] = 0.f; tf[13] = 0.f; tf[14] = 0.f; tf[15] = 1.f;
#pragma unroll
    for (int i = 0; i < 16; i++) {
        g_tf[p * 16 + i] = tf[i];
        if (write_out) out[1 + p * 16 + i] = tf[i];
    }
}

// ---------------- kernel 2: prepare point buffers + init minbuf -------------
__global__ void k_prep(const float* __restrict__ cad, const float* __restrict__ cam,
                       int P, int M, int N, int total) {
    int idx = blockIdx.x * blockDim.x + threadIdx.x;
    if (idx >= total) return;
    g_minbuf[idx] = 0x7f800000u;  // +inf

    float vx, vy, vz;
    if (idx < P * M) {
        int p = idx / M;
        const float* pt = cad + (size_t)idx * 3;
        const float* tf = g_tf + p * 16;
        float x = pt[0], y = pt[1], z = pt[2];
        vx = tf[0] * x + tf[1] * y + tf[2]  * z + tf[3];
        vy = tf[4] * x + tf[5] * y + tf[6]  * z + tf[7];
        vz = tf[8] * x + tf[9] * y + tf[10] * z + tf[11];
        float n2 = vx * vx + vy * vy + vz * vz;
        float* T = g_cadT + (size_t)idx * 8;
        T[0] = vx; T[1] = vx; T[2] = vy; T[3] = vy;
        T[4] = vz; T[5] = vz; T[6] = 0.5f * n2; T[7] = 0.5f * n2;
        g_cadQ[idx] = make_float4(vx, vy, vz, n2);
    } else {
        int j = idx - P * M;
        const float* pt = cam + (size_t)j * 3;
        vx = pt[0]; vy = pt[1]; vz = pt[2];
        float n2 = vx * vx + vy * vy + vz * vz;
        float* T = g_camT + (size_t)j * 8;
        T[0] = vx; T[1] = vx; T[2] = vy; T[3] = vy;
        T[4] = vz; T[5] = vz; T[6] = 0.5f * n2; T[7] = 0.5f * n2;
        g_camQ[j] = make_float4(vx, vy, vz, n2);
    }
}

// ---------------- kernel 2.5: reset ticket (also aligns ncu capture) --------
__global__ void k_tick() {
    if (threadIdx.x == 0) g_ticket = 0u;
}

// ---------------- kernel 3: chamfer (hot; persistent + work stealing) -------
__global__ void __launch_bounds__(256, 2) k_chamfer(int P, int M, int N,
                                                    int qcA, int tsA, int qcB, int tsB) {
    __shared__ __align__(16) float tile[TSL * 8];
    __shared__ int s_item;

    const int tid = threadIdx.x;
    const float INF = __int_as_float(0x7f800000);
    const int itemsA = P * qcA * tsA;
    const int itemsB = P * qcB * tsB;
    const int totalItems = itemsA + itemsB;

    for (;;) {
        __syncthreads();            // prev iter fully done with tile & s_item
        if (tid == 0) s_item = (int)atomicAdd(&g_ticket, 1u);
        __syncthreads();
        int item = s_item;
        if (item >= totalItems) break;

        int p, qc, sl, nq, nt, minoff;
        const float4* Q;
        const float*  T;
        if (item < itemsA) {
            p = item / (qcA * tsA); int r = item % (qcA * tsA); qc = r / tsA; sl = r % tsA;
            nq = M; nt = N;
            Q = g_cadQ + (size_t)p * M;
            T = g_camT + (size_t)p * N * 8;
            minoff = p * M;
        } else {
            int b1 = item - itemsA;
            p = b1 / (qcB * tsB); int r = b1 % (qcB * tsB); qc = r / tsB; sl = r % tsB;
            nq = N; nt = M;
            Q = g_camQ + (size_t)p * N;
            T = g_cadT + (size_t)p * M * 8;
            minoff = P * M + p * N;
        }

        // ---- load this thread's 8 query points (4 packed pairs) ----
        u64 qnx[4], qny[4], qnz[4];
        float mn0[4], mn1[4], x2a[4], x2b[4];
#pragma unroll
        for (int k = 0; k < 4; k++) {
            int i0 = qc * QCH + (2 * k) * 256 + tid;
            int i1 = i0 + 256;
            float4 A = (i0 < nq) ? Q[i0] : make_float4(0.f, 0.f, 0.f, INF);
            float4 B = (i1 < nq) ? Q[i1] : make_float4(0.f, 0.f, 0.f, INF);
            qnx[k] = pack2(-A.x, -B.x);
            qny[k] = pack2(-A.y, -B.y);
            qnz[k] = pack2(-A.z, -B.z);
            x2a[k] = A.w; x2b[k] = B.w;
            mn0[k] = INF; mn1[k] = INF;
        }

        // ---- cooperative tile load (1 float4 per thread at TSL=128) ----
        int tb = sl * TSL;
        int cnt = min(TSL, nt - tb);
        {
            const float4* src = (const float4*)(T + (size_t)tb * 8);
            float4* dst = (float4*)tile;
            for (int v = tid; v < cnt * 2; v += 256) dst[v] = src[v];
        }
        __syncthreads();

        // ---- main loop: 4 targets x 8 queries per iteration ----
        int j = 0;
        for (; j + 4 <= cnt; j += 4) {
            const float* tp = tile + j * 8;
            ulonglong2 a0 = *(const ulonglong2*)(tp);
            ulonglong2 a1 = *(const ulonglong2*)(tp + 4);
            ulonglong2 b0 = *(const ulonglong2*)(tp + 8);
            ulonglong2 b1 = *(const ulonglong2*)(tp + 12);
            ulonglong2 c0 = *(const ulonglong2*)(tp + 16);
            ulonglong2 c1 = *(const ulonglong2*)(tp + 20);
            ulonglong2 d0 = *(const ulonglong2*)(tp + 24);
            ulonglong2 d1 = *(const ulonglong2*)(tp + 28);
#pragma unroll
            for (int k = 0; k < 4; k++) {
                u64 gA = fma2(qnx[k], a0.x, a1.y);
                u64 gB = fma2(qnx[k], b0.x, b1.y);
                u64 gC = fma2(qnx[k], c0.x, c1.y);
                u64 gD = fma2(qnx[k], d0.x, d1.y);
                gA = fma2(qny[k], a0.y, gA);
                gB = fma2(qny[k], b0.y, gB);
                gC = fma2(qny[k], c0.y, gC);
                gD = fma2(qny[k], d0.y, gD);
                gA = fma2(qnz[k], a1.x, gA);
                gB = fma2(qnz[k], b1.x, gB);
                gC = fma2(qnz[k], c1.x, gC);
                gD = fma2(qnz[k], d1.x, gD);
                float alo, ahi, blo, bhi, clo, chi, dlo, dhi;
                unpack2(gA, alo, ahi); unpack2(gB, blo, bhi);
                unpack2(gC, clo, chi); unpack2(gD, dlo, dhi);
                float lo01 = fminf(alo, blo), lo23 = fminf(clo, dlo);
                float hi01 = fminf(ahi, bhi), hi23 = fminf(chi, dhi);
                mn0[k] = fminf(mn0[k], fminf(lo01, lo23));
                mn1[k] = fminf(mn1[k], fminf(hi01, hi23));
            }
        }
        for (; j < cnt; j++) {
            const float* tp = tile + j * 8;
            ulonglong2 a0 = *(const ulonglong2*)(tp);
            ulonglong2 a1 = *(const ulonglong2*)(tp + 4);
#pragma unroll
            for (int k = 0; k < 4; k++) {
                u64 gA = fma2(qnx[k], a0.x, a1.y);
                gA = fma2(qny[k], a0.y, gA);
                gA = fma2(qnz[k], a1.x, gA);
                float a_lo, a_hi;
                unpack2(gA, a_lo, a_hi);
                mn0[k] = fminf(mn0[k], a_lo);
                mn1[k] = fminf(mn1[k], a_hi);
            }
        }

        // ---- combine across slices: d2 = 2*g + |q|^2 (>=0), bitwise uint min ----
#pragma unroll
        for (int k = 0; k < 4; k++) {
            int i0 = qc * QCH + (2 * k) * 256 + tid;
            int i1 = i0 + 256;
            if (i0 < nq) {
                float d2 = fmaxf(fmaf(2.f, mn0[k], x2a[k]), 0.f);
                atomicMin(g_minbuf + minoff + i0, __float_as_uint(d2));
            }
            if (i1 < nq) {
                float d2 = fmaxf(fmaf(2.f, mn1[k], x2b[k]), 0.f);
                atomicMin(g_minbuf + minoff + i1, __float_as_uint(d2));
            }
        }
    }
}

// ---------------- kernel 4: weighted sqrt-sum partials -----------------------
__global__ void k_red(const float* __restrict__ w, int P, int M, int N) {
    __shared__ float sh[256];
    int total = P * (M + N);
    float s = 0.f;
    for (int e = blockIdx.x * 256 + threadIdx.x; e < total; e += NRED * 256) {
        int p; float invc;
        if (e < P * M) { p = e / M; invc = 1.0f / (float)M; }
        else           { p = (e - P * M) / N; invc = 1.0f / (float)N; }
        s += w[p] * invc * sqrtf(__uint_as_float(g_minbuf[e]));
    }
    sh[threadIdx.x] = s;
    __syncthreads();
    for (int o = 128; o > 0; o >>= 1) {
        if (threadIdx.x < o) sh[threadIdx.x] += sh[threadIdx.x + o];
        __syncthreads();
    }
    if (threadIdx.x == 0) g_partial[blockIdx.x] = sh[0];
}

// ---------------- kernel 5: deterministic final sum --------------------------
__global__ void k_fin(float* __restrict__ out) {
    if (threadIdx.x == 0) {
        float s = 0.f;
        for (int i = 0; i < NRED; i++) s += g_partial[i];
        out[0] = s;
    }
}

// ---------------- launcher ----------------------------------------------------
extern "C" void kernel_launch(void* const* d_in, const int* in_sizes, int n_in,
                              void* d_out, int out_size) {
    const float* cam  = (const float*)d_in[0];  // (P,N,3)
    const float* cad  = (const float*)d_in[1];  // (P,M,3)
    const float* wgt  = (const float*)d_in[2];  // (P,)
    const float* quat = (const float*)d_in[3];  // (P,4)
    const float* tra  = (const float*)d_in[4];  // (P,3,1)
    float* out = (float*)d_out;

    int P = in_sizes[2];
    int N = in_sizes[0] / (3 * P);
    int M = in_sizes[1] / (3 * P);
    int write_out = (out_size >= 1 + 16 * P) ? 1 : 0;

    k_tf<<<1, 32>>>(quat, tra, out, P, write_out);              // launch 0

    int total = P * (M + N);
    k_prep<<<(total + 255) / 256, 256>>>(cad, cam, P, M, N, total);  // launch 1

    k_tick<<<1, 32>>>();                                        // launch 2

    int qcA = (M + QCH - 1) / QCH, tsA = (N + TSL - 1) / TSL;
    int qcB = (N + QCH - 1) / QCH, tsB = (M + TSL - 1) / TSL;
    k_chamfer<<<NBLK, 256>>>(P, M, N, qcA, tsA, qcB, tsB);      // launch 3 (hot)

    k_red<<<NRED, 256>>>(wgt, P, M, N);                         // launch 4
    k_fin<<<1, 1>>>(out);                                       // launch 5
}